// round 14
// baseline (speedup 1.0000x reference)
#include <cuda_runtime.h>
#include <cuda_bf16.h>
#include <math.h>
#include <cstdint>

// ---------------- problem constants ----------------
constexpr int Bsz = 4;
constexpr int S   = 2048;
constexpr int D   = 1024;
constexpr int H   = 16;
constexpr int HD  = 64;
constexpr int TD  = 3 * D;     // 3072
constexpr int M   = Bsz * S;   // 8192

// ---------------- scratch (no allocations allowed) ----------------
__device__ __nv_bfloat16 g_qkvh[(size_t)M * TD];   // 48 MB  qkv hi split
__device__ __nv_bfloat16 g_qkvl[(size_t)M * TD];   // 48 MB  qkv lo split
__device__ __nv_bfloat16 g_Ah[(size_t)M * D];      // 16 MB
__device__ __nv_bfloat16 g_Al[(size_t)M * D];      // 16 MB
__device__ __nv_bfloat16 g_Bh[(size_t)TD * D];     //  6 MB (transposed [N][K])
__device__ __nv_bfloat16 g_Bl[(size_t)TD * D];     //  6 MB

// =====================================================================
// helpers
// =====================================================================
__device__ __forceinline__ uint32_t smem_u32(const void* p) {
    uint32_t a;
    asm("{ .reg .u64 t; cvta.to.shared.u64 t, %1; cvt.u32.u64 %0, t; }"
        : "=r"(a) : "l"(p));
    return a;
}
__device__ __forceinline__ void cp16(uint32_t s, const void* g) {
    asm volatile("cp.async.cg.shared.global [%0], [%1], 16;" :: "r"(s), "l"(g));
}
__device__ __forceinline__ void ldm4(uint32_t* r, uint32_t addr) {
    asm volatile("ldmatrix.sync.aligned.m8n8.x4.shared.b16 {%0,%1,%2,%3}, [%4];"
                 : "=r"(r[0]), "=r"(r[1]), "=r"(r[2]), "=r"(r[3]) : "r"(addr));
}
__device__ __forceinline__ void ldm4t(uint32_t* r, uint32_t addr) {
    asm volatile("ldmatrix.sync.aligned.m8n8.x4.trans.shared.b16 {%0,%1,%2,%3}, [%4];"
                 : "=r"(r[0]), "=r"(r[1]), "=r"(r[2]), "=r"(r[3]) : "r"(addr));
}
__device__ __forceinline__ void mma16816(float* c, const uint32_t* a, const uint32_t* b) {
    asm volatile(
        "mma.sync.aligned.m16n8k16.row.col.f32.bf16.bf16.f32 "
        "{%0,%1,%2,%3}, {%4,%5,%6,%7}, {%8,%9}, {%0,%1,%2,%3};"
        : "+f"(c[0]), "+f"(c[1]), "+f"(c[2]), "+f"(c[3])
        : "r"(a[0]), "r"(a[1]), "r"(a[2]), "r"(a[3]), "r"(b[0]), "r"(b[1]));
}
__device__ __forceinline__ uint32_t pack_bf(float a, float b) {
    uint32_t r;
    asm("cvt.rn.bf16x2.f32 %0, %1, %2;" : "=r"(r) : "f"(b), "f"(a));
    return r;
}
__device__ __forceinline__ uint32_t pack_lo(uint32_t hpk, float a, float b) {
    const float al = a - __uint_as_float(hpk << 16);
    const float bl = b - __uint_as_float(hpk & 0xFFFF0000u);
    return pack_bf(al, bl);
}

// =====================================================================
// split fp32 -> bf16 hi/lo (elementwise, vectorized x4)
// =====================================================================
__global__ __launch_bounds__(256) void split_bf16_kernel(
    const float* __restrict__ in,
    __nv_bfloat16* __restrict__ hi, __nv_bfloat16* __restrict__ lo, int n4)
{
    const int i = blockIdx.x * blockDim.x + threadIdx.x;
    if (i >= n4) return;
    const float4 v = ((const float4*)in)[i];
    float f[4] = {v.x, v.y, v.z, v.w};
    __nv_bfloat16 h[4], l[4];
#pragma unroll
    for (int j = 0; j < 4; ++j) {
        h[j] = __float2bfloat16_rn(f[j]);
        l[j] = __float2bfloat16_rn(f[j] - __bfloat162float(h[j]));
    }
    ((__nv_bfloat162*)hi)[2 * i]     = __nv_bfloat162{h[0], h[1]};
    ((__nv_bfloat162*)hi)[2 * i + 1] = __nv_bfloat162{h[2], h[3]};
    ((__nv_bfloat162*)lo)[2 * i]     = __nv_bfloat162{l[0], l[1]};
    ((__nv_bfloat162*)lo)[2 * i + 1] = __nv_bfloat162{l[2], l[3]};
}

// =====================================================================
// transpose + split:  in [K][N] fp32  ->  hi/lo [N][K] bf16
// =====================================================================
__global__ __launch_bounds__(256) void transpose_split_kernel(
    const float* __restrict__ in,
    __nv_bfloat16* __restrict__ hi, __nv_bfloat16* __restrict__ lo, int K, int N)
{
    __shared__ float t[32][33];
    const int n0 = blockIdx.x * 32, k0 = blockIdx.y * 32;
    const int tx = threadIdx.x, ty = threadIdx.y;
#pragma unroll
    for (int j = 0; j < 4; ++j)
        t[ty + j * 8][tx] = in[(size_t)(k0 + ty + j * 8) * N + n0 + tx];
    __syncthreads();
#pragma unroll
    for (int j = 0; j < 4; ++j) {
        const int row = ty + j * 8;
        const float v = t[tx][row];
        const __nv_bfloat16 h = __float2bfloat16_rn(v);
        const __nv_bfloat16 l = __float2bfloat16_rn(v - __bfloat162float(h));
        hi[(size_t)(n0 + row) * K + k0 + tx] = h;
        lo[(size_t)(n0 + row) * K + k0 + tx] = l;
    }
}

// =====================================================================
// bf16x3 tensor-core GEMM + bias via mma.sync.
// CTA 128x128, 128 threads = 4 warps of 64x64, 2 CTAs/SM.
// 2-stage cp.async pipeline with ONE __syncthreads per k-tile:
// the top-of-iteration barrier (after wait_group) also proves all warps
// finished reading stage (kt-1)&1 == (kt+1)&1, so ISSUE(kt+1) is placed
// right after it (overlapping compute of kt) and the trailing barrier
// is eliminated.
// Epilogue dual-mode:
//   Cl != nullptr: write bf16 hi/lo split (cols < scale_lim scaled by 0.125)
//   Cl == nullptr: write fp32 to C
// =====================================================================
constexpr int GTILE     = 128 * 80;               // 10240 per operand tile
constexpr int SSZ       = 4 * GTILE;              // Ah|Al|Bh|Bl = 40960/stage
constexpr int GEMM_SMEM = 2 * SSZ;                // 81920

__global__ __launch_bounds__(128, 2) void gemm_bf16x3_kernel(
    const __nv_bfloat16* __restrict__ Ah, const __nv_bfloat16* __restrict__ Al,
    const __nv_bfloat16* __restrict__ Bh, const __nv_bfloat16* __restrict__ Bl,
    const float* __restrict__ bias, float* __restrict__ C,
    __nv_bfloat16* __restrict__ Ch, __nv_bfloat16* __restrict__ Cl,
    int N, int K, int scale_lim)
{
    extern __shared__ char smem[];
    const uint32_t sb = smem_u32(smem);
    const int tid  = threadIdx.x;
    const int lane = tid & 31, wid = tid >> 5;
    const int wm = wid & 1, wn = wid >> 1;          // 2 x 2 warps of 64x64
    const int bm = blockIdx.y * 128, bn = blockIdx.x * 128;

    // loader: 512 rows (Ah128|Al128|Bh128|Bl128) x 4 chunks of 16B, 128 thr
    const int lc = tid & 3, lrow = tid >> 2;        // chunk, row-group 0..31

#define ISSUE(kt, st) do {                                                       \
    const uint32_t stb = sb + (uint32_t)(st) * (uint32_t)SSZ;                    \
    _Pragma("unroll")                                                            \
    for (int it = 0; it < 16; ++it) {                                            \
        const int tile = it >> 2;                                                \
        const int r = lrow + (it & 3) * 32;                                      \
        const __nv_bfloat16* base =                                              \
            (tile == 0) ? Ah : (tile == 1) ? Al : (tile == 2) ? Bh : Bl;         \
        const __nv_bfloat16* src = base                                          \
            + (size_t)((tile < 2 ? bm : bn) + r) * K + (kt) * 32 + lc * 8;       \
        cp16(stb + (uint32_t)(tile * GTILE + r * 80 + lc * 16), src);            \
    }                                                                            \
    asm volatile("cp.async.commit_group;" ::: "memory");                         \
} while (0)

    float acc[4][8][4];
#pragma unroll
    for (int a = 0; a < 4; ++a)
#pragma unroll
        for (int b = 0; b < 8; ++b)
#pragma unroll
            for (int c = 0; c < 4; ++c) acc[a][b][c] = 0.0f;

    const uint32_t aoff = (uint32_t)((lane & 15) * 80 + (lane >> 4) * 16);
    const uint32_t boff = (uint32_t)(((lane & 7) + ((lane >> 4) << 3)) * 80 +
                                     ((lane >> 3) & 1) * 16);

    const int NT = K / 32;
    ISSUE(0, 0);

    for (int kt = 0; kt < NT; ++kt) {
        asm volatile("cp.async.wait_group 0;" ::: "memory");
        __syncthreads();   // stage kt&1 visible to all; stage (kt+1)&1 drained
        if (kt + 1 < NT) ISSUE(kt + 1, (kt + 1) & 1);

        const uint32_t stb = sb + (uint32_t)(kt & 1) * (uint32_t)SSZ;
        const uint32_t pAh = stb + (uint32_t)(wm * 64 * 80) + aoff;
        const uint32_t pAl = pAh + (uint32_t)GTILE;
        const uint32_t pBh = stb + 2u * GTILE + (uint32_t)(wn * 64 * 80) + boff;
        const uint32_t pBl = pBh + (uint32_t)GTILE;

#pragma unroll
        for (int ks = 0; ks < 2; ++ks) {
            const uint32_t ko = (uint32_t)(ks * 32);
            uint32_t ah[4][4], al[4][4];
#pragma unroll
            for (int mi = 0; mi < 4; ++mi) {
                ldm4(ah[mi], pAh + (uint32_t)(mi * 1280) + ko);
                ldm4(al[mi], pAl + (uint32_t)(mi * 1280) + ko);
            }
#pragma unroll
            for (int g = 0; g < 4; ++g) {
                uint32_t bh[4], bl[4];
                ldm4(bh, pBh + (uint32_t)(g * 1280) + ko);
                ldm4(bl, pBl + (uint32_t)(g * 1280) + ko);
#pragma unroll
                for (int mi = 0; mi < 4; ++mi) {
                    mma16816(acc[mi][2 * g],     ah[mi], &bh[0]);
                    mma16816(acc[mi][2 * g],     ah[mi], &bl[0]);
                    mma16816(acc[mi][2 * g],     al[mi], &bh[0]);
                    mma16816(acc[mi][2 * g + 1], ah[mi], &bh[2]);
                    mma16816(acc[mi][2 * g + 1], ah[mi], &bl[2]);
                    mma16816(acc[mi][2 * g + 1], al[mi], &bh[2]);
                }
            }
        }
    }
#undef ISSUE

#pragma unroll
    for (int mi = 0; mi < 4; ++mi) {
        const int row0 = bm + wm * 64 + mi * 16 + (lane >> 2);
#pragma unroll
        for (int nj = 0; nj < 8; ++nj) {
            const int col = bn + wn * 64 + nj * 8 + (lane & 3) * 2;
            const float bx = bias[col], by = bias[col + 1];
            float v0 = acc[mi][nj][0] + bx, v1 = acc[mi][nj][1] + by;
            float v2 = acc[mi][nj][2] + bx, v3 = acc[mi][nj][3] + by;
            if (Cl) {
                const float sc = (col < scale_lim) ? 0.125f : 1.0f;  // fold 1/sqrt(hd) into Q
                v0 *= sc; v1 *= sc; v2 *= sc; v3 *= sc;
                const uint32_t h01 = pack_bf(v0, v1), h23 = pack_bf(v2, v3);
                *(uint32_t*)&Ch[(size_t)row0 * N + col]       = h01;
                *(uint32_t*)&Ch[(size_t)(row0 + 8) * N + col] = h23;
                *(uint32_t*)&Cl[(size_t)row0 * N + col]       = pack_lo(h01, v0, v1);
                *(uint32_t*)&Cl[(size_t)(row0 + 8) * N + col] = pack_lo(h23, v2, v3);
            } else {
                float2 a0{v0, v1}, a1{v2, v3};
                *(float2*)&C[(size_t)row0 * N + col]       = a0;
                *(float2*)&C[(size_t)(row0 + 8) * N + col] = a1;
            }
        }
    }
}

// =====================================================================
// Causal flash attention, bf16x3 mma.sync, cp.async double-buffered K/V.
// (unchanged from R13 passing version)
// =====================================================================
constexpr int APITCH = 144;
constexpr int KVBUF  = 4 * 64 * APITCH;                   // 36864
constexpr int ATTN2_SMEM = 2 * 128 * APITCH + 2 * KVBUF;  // 110592

__global__ __launch_bounds__(256) void attn_mma_kernel(
    const __nv_bfloat16* __restrict__ qkvh, const __nv_bfloat16* __restrict__ qkvl,
    __nv_bfloat16* __restrict__ Ahd, __nv_bfloat16* __restrict__ Ald)
{
    extern __shared__ char smn[];
    const uint32_t sb = smem_u32(smn);
    const int tid = threadIdx.x, lane = tid & 31, wid = tid >> 5;
    const int qt = (gridDim.x - 1) - blockIdx.x;   // heavy tiles first
    const int h = blockIdx.y, b = blockIdx.z;
    const int q0 = qt * 128;

    const size_t rowbase = (size_t)b * S * TD + h * HD;

    // coalesced loader coords: 8 threads per 128B row segment
    const int lc = tid & 7;          // chunk within row (16B each)
    const int lr = tid >> 3;         // row group 0..31

    // ---- issue Q tile loads (hi+lo), async, coalesced ----
#pragma unroll
    for (int ii = 0; ii < 8; ++ii) {
        const int comp = ii >> 2;                  // 0=hi, 1=lo
        const int r = lr + (ii & 3) * 32;          // 0..127
        const __nv_bfloat16* src = (comp ? qkvl : qkvh) + rowbase
                                 + (size_t)(q0 + r) * TD + lc * 8;
        cp16(sb + (uint32_t)(comp * 18432 + r * APITCH + lc * 16), src);
    }

    // ---- K/V loader: comp 0=Kh 1=Kl 2=Vh 3=Vl, coalesced ----
#define KV_ISSUE(jt_, buf_) do {                                                 \
    _Pragma("unroll")                                                            \
    for (int ii = 0; ii < 8; ++ii) {                                             \
        const int comp = ii >> 1;                                                \
        const int r = lr + (ii & 1) * 32;          /* 0..63 */                   \
        const __nv_bfloat16* src = ((comp & 1) ? qkvl : qkvh) + rowbase          \
            + ((comp >> 1) ? 2 * D : D)                                          \
            + (size_t)((jt_) * 64 + r) * TD + lc * 8;                            \
        cp16(sb + 36864u + (uint32_t)(buf_) * (uint32_t)KVBUF                    \
             + (uint32_t)(comp * 9216 + r * APITCH + lc * 16), src);             \
    }                                                                            \
    asm volatile("cp.async.commit_group;" ::: "memory");                         \
} while (0)

    const int ktiles = 2 * qt + 2;
    KV_ISSUE(0, 0);                    // group 0: Q + KV tile 0
    if (ktiles > 1) KV_ISSUE(1, 1);    // group 1: KV tile 1

    // fragment address offsets (pitch 144)
    const uint32_t aoff = (uint32_t)((lane & 15) * APITCH + (lane >> 4) * 16);
    const uint32_t boff = (uint32_t)(((lane & 7) + ((lane >> 4) << 3)) * APITCH +
                                     ((lane >> 3) & 1) * 16);
    const uint32_t voff = (uint32_t)(((lane & 7) + (((lane >> 3) & 1) << 3)) * APITCH +
                                     (lane >> 4) * 16);
    const uint32_t qh_base = sb + (uint32_t)(wid * 16 * APITCH) + aoff;
    const uint32_t ql_base = qh_base + 18432;

    float o[8][4];
#pragma unroll
    for (int nj = 0; nj < 8; ++nj)
#pragma unroll
        for (int c = 0; c < 4; ++c) o[nj][c] = 0.0f;
    float m0 = -1e30f, m1 = -1e30f, l0 = 0.0f, l1 = 0.0f;

    for (int jt = 0; jt < ktiles; ++jt) {
        if (jt + 1 < ktiles)
            asm volatile("cp.async.wait_group 1;" ::: "memory");
        else
            asm volatile("cp.async.wait_group 0;" ::: "memory");
        __syncthreads();

        const uint32_t kvb = sb + 36864u + (uint32_t)(jt & 1) * (uint32_t)KVBUF;

        // ---- S = Q @ K^T (bf16x3; Q pre-scaled by 0.125) ----
        float s[8][4];
#pragma unroll
        for (int nj = 0; nj < 8; ++nj)
#pragma unroll
            for (int c = 0; c < 4; ++c) s[nj][c] = 0.0f;

#pragma unroll
        for (int kc = 0; kc < 4; ++kc) {
            uint32_t ah[4], al[4];
            ldm4(ah, qh_base + kc * 32);
            ldm4(al, ql_base + kc * 32);
#pragma unroll
            for (int kg = 0; kg < 4; ++kg) {
                uint32_t bh[4], bl[4];
                ldm4(bh, kvb + (uint32_t)(kg * 16 * APITCH) + boff + kc * 32);
                ldm4(bl, kvb + 9216u + (uint32_t)(kg * 16 * APITCH) + boff + kc * 32);
                mma16816(s[2 * kg],     ah, &bh[0]);
                mma16816(s[2 * kg],     ah, &bl[0]);
                mma16816(s[2 * kg],     al, &bh[0]);
                mma16816(s[2 * kg + 1], ah, &bh[2]);
                mma16816(s[2 * kg + 1], ah, &bl[2]);
                mma16816(s[2 * kg + 1], al, &bh[2]);
            }
        }

        // ---- causal mask (only the last two diagonal tiles need it) ----
        const int gr0 = q0 + wid * 16 + (lane >> 2);
        const int gr1 = gr0 + 8;
        if (jt >= 2 * qt) {
            const int k0 = jt * 64;
#pragma unroll
            for (int nj = 0; nj < 8; ++nj) {
                const int gc = k0 + nj * 8 + (lane & 3) * 2;
                if (gc     > gr0) s[nj][0] = -10000.0f;
                if (gc + 1 > gr0) s[nj][1] = -10000.0f;
                if (gc     > gr1) s[nj][2] = -10000.0f;
                if (gc + 1 > gr1) s[nj][3] = -10000.0f;
            }
        }

        // ---- streaming softmax ----
        float mx0 = -1e30f, mx1 = -1e30f;
#pragma unroll
        for (int nj = 0; nj < 8; ++nj) {
            mx0 = fmaxf(mx0, fmaxf(s[nj][0], s[nj][1]));
            mx1 = fmaxf(mx1, fmaxf(s[nj][2], s[nj][3]));
        }
        mx0 = fmaxf(mx0, __shfl_xor_sync(0xffffffffu, mx0, 1));
        mx0 = fmaxf(mx0, __shfl_xor_sync(0xffffffffu, mx0, 2));
        mx1 = fmaxf(mx1, __shfl_xor_sync(0xffffffffu, mx1, 1));
        mx1 = fmaxf(mx1, __shfl_xor_sync(0xffffffffu, mx1, 2));

        const float mn0 = fmaxf(m0, mx0), mn1 = fmaxf(m1, mx1);
        const float f0 = __expf(m0 - mn0), f1 = __expf(m1 - mn1);

        float rs0 = 0.0f, rs1 = 0.0f;
#pragma unroll
        for (int nj = 0; nj < 8; ++nj) {
            s[nj][0] = __expf(s[nj][0] - mn0);
            s[nj][1] = __expf(s[nj][1] - mn0);
            s[nj][2] = __expf(s[nj][2] - mn1);
            s[nj][3] = __expf(s[nj][3] - mn1);
            rs0 += s[nj][0] + s[nj][1];
            rs1 += s[nj][2] + s[nj][3];
        }
        rs0 += __shfl_xor_sync(0xffffffffu, rs0, 1);
        rs0 += __shfl_xor_sync(0xffffffffu, rs0, 2);
        rs1 += __shfl_xor_sync(0xffffffffu, rs1, 1);
        rs1 += __shfl_xor_sync(0xffffffffu, rs1, 2);

        l0 = l0 * f0 + rs0;  m0 = mn0;
        l1 = l1 * f1 + rs1;  m1 = mn1;
#pragma unroll
        for (int nj = 0; nj < 8; ++nj) {
            o[nj][0] *= f0; o[nj][1] *= f0;
            o[nj][2] *= f1; o[nj][3] *= f1;
        }

        // ---- O += P @ V (P packed in-register, bf16x3) ----
#pragma unroll
        for (int kc2 = 0; kc2 < 4; ++kc2) {
            uint32_t ph[4], pl[4];
            ph[0] = pack_bf(s[2 * kc2][0],     s[2 * kc2][1]);
            ph[1] = pack_bf(s[2 * kc2][2],     s[2 * kc2][3]);
            ph[2] = pack_bf(s[2 * kc2 + 1][0], s[2 * kc2 + 1][1]);
            ph[3] = pack_bf(s[2 * kc2 + 1][2], s[2 * kc2 + 1][3]);
            pl[0] = pack_lo(ph[0], s[2 * kc2][0],     s[2 * kc2][1]);
            pl[1] = pack_lo(ph[1], s[2 * kc2][2],     s[2 * kc2][3]);
            pl[2] = pack_lo(ph[2], s[2 * kc2 + 1][0], s[2 * kc2 + 1][1]);
            pl[3] = pack_lo(ph[3], s[2 * kc2 + 1][2], s[2 * kc2 + 1][3]);
#pragma unroll
            for (int vg = 0; vg < 4; ++vg) {
                uint32_t vh[4], vl[4];
                ldm4t(vh, kvb + 18432u + (uint32_t)(kc2 * 16 * APITCH) + voff + vg * 32);
                ldm4t(vl, kvb + 27648u + (uint32_t)(kc2 * 16 * APITCH) + voff + vg * 32);
                mma16816(o[2 * vg],     ph, &vh[0]);
                mma16816(o[2 * vg],     ph, &vl[0]);
                mma16816(o[2 * vg],     pl, &vh[0]);
                mma16816(o[2 * vg + 1], ph, &vh[2]);
                mma16816(o[2 * vg + 1], ph, &vl[2]);
                mma16816(o[2 * vg + 1], pl, &vh[2]);
            }
        }

        __syncthreads();   // readers done before reissuing into this buffer
        if (jt + 2 < ktiles) KV_ISSUE(jt + 2, (jt & 1));
    }
#undef KV_ISSUE

    // ---- epilogue: normalize, split bf16 hi/lo, merged-head layout ----
    const float i0 = 1.0f / l0, i1 = 1.0f / l1;
    const int r0 = q0 + wid * 16 + (lane >> 2);
    const size_t g0 = ((size_t)b * S + r0) * D + h * HD;
    const size_t g1 = g0 + (size_t)8 * D;
#pragma unroll
    for (int nj = 0; nj < 8; ++nj) {
        const int col = nj * 8 + (lane & 3) * 2;
        const float v0 = o[nj][0] * i0, v1 = o[nj][1] * i0;
        const float v2 = o[nj][2] * i1, v3 = o[nj][3] * i1;
        const uint32_t h01 = pack_bf(v0, v1), h23 = pack_bf(v2, v3);
        *(uint32_t*)&Ahd[g0 + col] = h01;
        *(uint32_t*)&Ahd[g1 + col] = h23;
        *(uint32_t*)&Ald[g0 + col] = pack_lo(h01, v0, v1);
        *(uint32_t*)&Ald[g1 + col] = pack_lo(h23, v2, v3);
    }
}

// =====================================================================
// launch
// =====================================================================
extern "C" void kernel_launch(void* const* d_in, const int* in_sizes, int n_in,
                              void* d_out, int out_size)
{
    const float* hs     = (const float*)d_in[0];
    const float* w_attn = (const float*)d_in[1];
    const float* b_attn = (const float*)d_in[2];
    const float* w_proj = (const float*)d_in[3];
    const float* b_proj = (const float*)d_in[4];
    float* out = (float*)d_out;

    __nv_bfloat16 *qkvh, *qkvl, *Ah, *Al, *Bh, *Bl;
    cudaGetSymbolAddress((void**)&qkvh, g_qkvh);
    cudaGetSymbolAddress((void**)&qkvl, g_qkvl);
    cudaGetSymbolAddress((void**)&Ah, g_Ah);
    cudaGetSymbolAddress((void**)&Al, g_Al);
    cudaGetSymbolAddress((void**)&Bh, g_Bh);
    cudaGetSymbolAddress((void**)&Bl, g_Bl);

    cudaFuncSetAttribute(gemm_bf16x3_kernel,
                         cudaFuncAttributeMaxDynamicSharedMemorySize, GEMM_SMEM);
    cudaFuncSetAttribute(attn_mma_kernel,
                         cudaFuncAttributeMaxDynamicSharedMemorySize, ATTN2_SMEM);

    // --- stage 1: QKV projection -> bf16 hi/lo split, Q pre-scaled by 0.125 ---
    split_bf16_kernel<<<(M * D / 4 + 255) / 256, 256>>>(hs, Ah, Al, M * D / 4);
    transpose_split_kernel<<<dim3(TD / 32, D / 32), dim3(32, 8)>>>(w_attn, Bh, Bl, D, TD);
    dim3 g1(TD / 128, M / 128);        // (24, 64)
    gemm_bf16x3_kernel<<<g1, 128, GEMM_SMEM>>>(Ah, Al, Bh, Bl, b_attn,
                                               nullptr, qkvh, qkvl, TD, D, D);

    // --- stage 2: causal flash attention (cp.async double-buffered, coalesced) ---
    dim3 g2(S / 128, H, Bsz);          // (16, 16, 4)
    attn_mma_kernel<<<g2, 256, ATTN2_SMEM>>>(qkvh, qkvl, Ah, Al);

    // --- stage 3: output projection -> fp32 out ---
    transpose_split_kernel<<<dim3(D / 32, D / 32), dim3(32, 8)>>>(w_proj, Bh, Bl, D, D);
    dim3 g3(D / 128, M / 128);         // (8, 64)
    gemm_bf16x3_kernel<<<g3, 128, GEMM_SMEM>>>(Ah, Al, Bh, Bl, b_proj,
                                               out, nullptr, nullptr, D, D, 0);
}

// round 17
// speedup vs baseline: 1.5421x; 1.5421x over previous
#include <cuda_runtime.h>
#include <cuda_bf16.h>
#include <math.h>
#include <cstdint>

// ---------------- problem constants ----------------
constexpr int Bsz = 4;
constexpr int S   = 2048;
constexpr int D   = 1024;
constexpr int H   = 16;
constexpr int HD  = 64;
constexpr int TD  = 3 * D;     // 3072
constexpr int M   = Bsz * S;   // 8192

// ---------------- scratch (no allocations allowed) ----------------
__device__ __nv_bfloat16 g_qkvh[(size_t)M * TD];   // 48 MB  qkv hi split
__device__ __nv_bfloat16 g_qkvl[(size_t)M * TD];   // 48 MB  qkv lo split
__device__ __nv_bfloat16 g_Ah[(size_t)M * D];      // 16 MB
__device__ __nv_bfloat16 g_Al[(size_t)M * D];      // 16 MB
__device__ __nv_bfloat16 g_Bh[(size_t)TD * D];     //  6 MB (transposed [N][K])
__device__ __nv_bfloat16 g_Bl[(size_t)TD * D];     //  6 MB

// =====================================================================
// helpers
// =====================================================================
__device__ __forceinline__ uint32_t smem_u32(const void* p) {
    uint32_t a;
    asm("{ .reg .u64 t; cvta.to.shared.u64 t, %1; cvt.u32.u64 %0, t; }"
        : "=r"(a) : "l"(p));
    return a;
}
__device__ __forceinline__ void cp16(uint32_t s, const void* g) {
    asm volatile("cp.async.cg.shared.global [%0], [%1], 16;" :: "r"(s), "l"(g));
}
__device__ __forceinline__ void ldm4(uint32_t* r, uint32_t addr) {
    asm volatile("ldmatrix.sync.aligned.m8n8.x4.shared.b16 {%0,%1,%2,%3}, [%4];"
                 : "=r"(r[0]), "=r"(r[1]), "=r"(r[2]), "=r"(r[3]) : "r"(addr));
}
__device__ __forceinline__ void ldm4t(uint32_t* r, uint32_t addr) {
    asm volatile("ldmatrix.sync.aligned.m8n8.x4.trans.shared.b16 {%0,%1,%2,%3}, [%4];"
                 : "=r"(r[0]), "=r"(r[1]), "=r"(r[2]), "=r"(r[3]) : "r"(addr));
}
__device__ __forceinline__ void mma16816(float* c, const uint32_t* a, const uint32_t* b) {
    asm volatile(
        "mma.sync.aligned.m16n8k16.row.col.f32.bf16.bf16.f32 "
        "{%0,%1,%2,%3}, {%4,%5,%6,%7}, {%8,%9}, {%0,%1,%2,%3};"
        : "+f"(c[0]), "+f"(c[1]), "+f"(c[2]), "+f"(c[3])
        : "r"(a[0]), "r"(a[1]), "r"(a[2]), "r"(a[3]), "r"(b[0]), "r"(b[1]));
}
__device__ __forceinline__ uint32_t pack_bf(float a, float b) {
    uint32_t r;
    asm("cvt.rn.bf16x2.f32 %0, %1, %2;" : "=r"(r) : "f"(b), "f"(a));
    return r;
}
__device__ __forceinline__ uint32_t pack_lo(uint32_t hpk, float a, float b) {
    const float al = a - __uint_as_float(hpk << 16);
    const float bl = b - __uint_as_float(hpk & 0xFFFF0000u);
    return pack_bf(al, bl);
}

// =====================================================================
// split fp32 -> bf16 hi/lo (elementwise, vectorized x4)
// =====================================================================
__global__ __launch_bounds__(256) void split_bf16_kernel(
    const float* __restrict__ in,
    __nv_bfloat16* __restrict__ hi, __nv_bfloat16* __restrict__ lo, int n4)
{
    const int i = blockIdx.x * blockDim.x + threadIdx.x;
    if (i >= n4) return;
    const float4 v = ((const float4*)in)[i];
    float f[4] = {v.x, v.y, v.z, v.w};
    __nv_bfloat16 h[4], l[4];
#pragma unroll
    for (int j = 0; j < 4; ++j) {
        h[j] = __float2bfloat16_rn(f[j]);
        l[j] = __float2bfloat16_rn(f[j] - __bfloat162float(h[j]));
    }
    ((__nv_bfloat162*)hi)[2 * i]     = __nv_bfloat162{h[0], h[1]};
    ((__nv_bfloat162*)hi)[2 * i + 1] = __nv_bfloat162{h[2], h[3]};
    ((__nv_bfloat162*)lo)[2 * i]     = __nv_bfloat162{l[0], l[1]};
    ((__nv_bfloat162*)lo)[2 * i + 1] = __nv_bfloat162{l[2], l[3]};
}

// =====================================================================
// transpose + split:  in [K][N] fp32  ->  hi/lo [N][K] bf16
// =====================================================================
__global__ __launch_bounds__(256) void transpose_split_kernel(
    const float* __restrict__ in,
    __nv_bfloat16* __restrict__ hi, __nv_bfloat16* __restrict__ lo, int K, int N)
{
    __shared__ float t[32][33];
    const int n0 = blockIdx.x * 32, k0 = blockIdx.y * 32;
    const int tx = threadIdx.x, ty = threadIdx.y;
#pragma unroll
    for (int j = 0; j < 4; ++j)
        t[ty + j * 8][tx] = in[(size_t)(k0 + ty + j * 8) * N + n0 + tx];
    __syncthreads();
#pragma unroll
    for (int j = 0; j < 4; ++j) {
        const int row = ty + j * 8;
        const float v = t[tx][row];
        const __nv_bfloat16 h = __float2bfloat16_rn(v);
        const __nv_bfloat16 l = __float2bfloat16_rn(v - __bfloat162float(h));
        hi[(size_t)(n0 + row) * K + k0 + tx] = h;
        lo[(size_t)(n0 + row) * K + k0 + tx] = l;
    }
}

// =====================================================================
// bf16x3 tensor-core GEMM + bias via mma.sync.
// CTA 128x128, 128 threads = 4 warps of 64x64, 2 CTAs/SM.
// 2-stage cp.async pipeline with ONE __syncthreads per k-tile.
// (unchanged from R14; R14's bench was clock-confounded — attn control
// showed the whole run at ~63% clock. Re-measuring.)
// =====================================================================
constexpr int GTILE     = 128 * 80;               // 10240 per operand tile
constexpr int SSZ       = 4 * GTILE;              // Ah|Al|Bh|Bl = 40960/stage
constexpr int GEMM_SMEM = 2 * SSZ;                // 81920

__global__ __launch_bounds__(128, 2) void gemm_bf16x3_kernel(
    const __nv_bfloat16* __restrict__ Ah, const __nv_bfloat16* __restrict__ Al,
    const __nv_bfloat16* __restrict__ Bh, const __nv_bfloat16* __restrict__ Bl,
    const float* __restrict__ bias, float* __restrict__ C,
    __nv_bfloat16* __restrict__ Ch, __nv_bfloat16* __restrict__ Cl,
    int N, int K, int scale_lim)
{
    extern __shared__ char smem[];
    const uint32_t sb = smem_u32(smem);
    const int tid  = threadIdx.x;
    const int lane = tid & 31, wid = tid >> 5;
    const int wm = wid & 1, wn = wid >> 1;          // 2 x 2 warps of 64x64
    const int bm = blockIdx.y * 128, bn = blockIdx.x * 128;

    // loader: 512 rows (Ah128|Al128|Bh128|Bl128) x 4 chunks of 16B, 128 thr
    const int lc = tid & 3, lrow = tid >> 2;        // chunk, row-group 0..31

#define ISSUE(kt, st) do {                                                       \
    const uint32_t stb = sb + (uint32_t)(st) * (uint32_t)SSZ;                    \
    _Pragma("unroll")                                                            \
    for (int it = 0; it < 16; ++it) {                                            \
        const int tile = it >> 2;                                                \
        const int r = lrow + (it & 3) * 32;                                      \
        const __nv_bfloat16* base =                                              \
            (tile == 0) ? Ah : (tile == 1) ? Al : (tile == 2) ? Bh : Bl;         \
        const __nv_bfloat16* src = base                                          \
            + (size_t)((tile < 2 ? bm : bn) + r) * K + (kt) * 32 + lc * 8;       \
        cp16(stb + (uint32_t)(tile * GTILE + r * 80 + lc * 16), src);            \
    }                                                                            \
    asm volatile("cp.async.commit_group;" ::: "memory");                         \
} while (0)

    float acc[4][8][4];
#pragma unroll
    for (int a = 0; a < 4; ++a)
#pragma unroll
        for (int b = 0; b < 8; ++b)
#pragma unroll
            for (int c = 0; c < 4; ++c) acc[a][b][c] = 0.0f;

    const uint32_t aoff = (uint32_t)((lane & 15) * 80 + (lane >> 4) * 16);
    const uint32_t boff = (uint32_t)(((lane & 7) + ((lane >> 4) << 3)) * 80 +
                                     ((lane >> 3) & 1) * 16);

    const int NT = K / 32;
    ISSUE(0, 0);

    for (int kt = 0; kt < NT; ++kt) {
        asm volatile("cp.async.wait_group 0;" ::: "memory");
        __syncthreads();   // stage kt&1 visible to all; stage (kt+1)&1 drained
        if (kt + 1 < NT) ISSUE(kt + 1, (kt + 1) & 1);

        const uint32_t stb = sb + (uint32_t)(kt & 1) * (uint32_t)SSZ;
        const uint32_t pAh = stb + (uint32_t)(wm * 64 * 80) + aoff;
        const uint32_t pAl = pAh + (uint32_t)GTILE;
        const uint32_t pBh = stb + 2u * GTILE + (uint32_t)(wn * 64 * 80) + boff;
        const uint32_t pBl = pBh + (uint32_t)GTILE;

#pragma unroll
        for (int ks = 0; ks < 2; ++ks) {
            const uint32_t ko = (uint32_t)(ks * 32);
            uint32_t ah[4][4], al[4][4];
#pragma unroll
            for (int mi = 0; mi < 4; ++mi) {
                ldm4(ah[mi], pAh + (uint32_t)(mi * 1280) + ko);
                ldm4(al[mi], pAl + (uint32_t)(mi * 1280) + ko);
            }
#pragma unroll
            for (int g = 0; g < 4; ++g) {
                uint32_t bh[4], bl[4];
                ldm4(bh, pBh + (uint32_t)(g * 1280) + ko);
                ldm4(bl, pBl + (uint32_t)(g * 1280) + ko);
#pragma unroll
                for (int mi = 0; mi < 4; ++mi) {
                    mma16816(acc[mi][2 * g],     ah[mi], &bh[0]);
                    mma16816(acc[mi][2 * g],     ah[mi], &bl[0]);
                    mma16816(acc[mi][2 * g],     al[mi], &bh[0]);
                    mma16816(acc[mi][2 * g + 1], ah[mi], &bh[2]);
                    mma16816(acc[mi][2 * g + 1], ah[mi], &bl[2]);
                    mma16816(acc[mi][2 * g + 1], al[mi], &bh[2]);
                }
            }
        }
    }
#undef ISSUE

#pragma unroll
    for (int mi = 0; mi < 4; ++mi) {
        const int row0 = bm + wm * 64 + mi * 16 + (lane >> 2);
#pragma unroll
        for (int nj = 0; nj < 8; ++nj) {
            const int col = bn + wn * 64 + nj * 8 + (lane & 3) * 2;
            const float bx = bias[col], by = bias[col + 1];
            float v0 = acc[mi][nj][0] + bx, v1 = acc[mi][nj][1] + by;
            float v2 = acc[mi][nj][2] + bx, v3 = acc[mi][nj][3] + by;
            if (Cl) {
                const float sc = (col < scale_lim) ? 0.125f : 1.0f;  // fold 1/sqrt(hd) into Q
                v0 *= sc; v1 *= sc; v2 *= sc; v3 *= sc;
                const uint32_t h01 = pack_bf(v0, v1), h23 = pack_bf(v2, v3);
                *(uint32_t*)&Ch[(size_t)row0 * N + col]       = h01;
                *(uint32_t*)&Ch[(size_t)(row0 + 8) * N + col] = h23;
                *(uint32_t*)&Cl[(size_t)row0 * N + col]       = pack_lo(h01, v0, v1);
                *(uint32_t*)&Cl[(size_t)(row0 + 8) * N + col] = pack_lo(h23, v2, v3);
            } else {
                float2 a0{v0, v1}, a1{v2, v3};
                *(float2*)&C[(size_t)row0 * N + col]       = a0;
                *(float2*)&C[(size_t)(row0 + 8) * N + col] = a1;
            }
        }
    }
}

// =====================================================================
// Causal flash attention, bf16x3 mma.sync, cp.async double-buffered K/V.
// (unchanged — serves as in-run clock control)
// =====================================================================
constexpr int APITCH = 144;
constexpr int KVBUF  = 4 * 64 * APITCH;                   // 36864
constexpr int ATTN2_SMEM = 2 * 128 * APITCH + 2 * KVBUF;  // 110592

__global__ __launch_bounds__(256) void attn_mma_kernel(
    const __nv_bfloat16* __restrict__ qkvh, const __nv_bfloat16* __restrict__ qkvl,
    __nv_bfloat16* __restrict__ Ahd, __nv_bfloat16* __restrict__ Ald)
{
    extern __shared__ char smn[];
    const uint32_t sb = smem_u32(smn);
    const int tid = threadIdx.x, lane = tid & 31, wid = tid >> 5;
    const int qt = (gridDim.x - 1) - blockIdx.x;   // heavy tiles first
    const int h = blockIdx.y, b = blockIdx.z;
    const int q0 = qt * 128;

    const size_t rowbase = (size_t)b * S * TD + h * HD;

    // coalesced loader coords: 8 threads per 128B row segment
    const int lc = tid & 7;          // chunk within row (16B each)
    const int lr = tid >> 3;         // row group 0..31

    // ---- issue Q tile loads (hi+lo), async, coalesced ----
#pragma unroll
    for (int ii = 0; ii < 8; ++ii) {
        const int comp = ii >> 2;                  // 0=hi, 1=lo
        const int r = lr + (ii & 3) * 32;          // 0..127
        const __nv_bfloat16* src = (comp ? qkvl : qkvh) + rowbase
                                 + (size_t)(q0 + r) * TD + lc * 8;
        cp16(sb + (uint32_t)(comp * 18432 + r * APITCH + lc * 16), src);
    }

    // ---- K/V loader: comp 0=Kh 1=Kl 2=Vh 3=Vl, coalesced ----
#define KV_ISSUE(jt_, buf_) do {                                                 \
    _Pragma("unroll")                                                            \
    for (int ii = 0; ii < 8; ++ii) {                                             \
        const int comp = ii >> 1;                                                \
        const int r = lr + (ii & 1) * 32;          /* 0..63 */                   \
        const __nv_bfloat16* src = ((comp & 1) ? qkvl : qkvh) + rowbase          \
            + ((comp >> 1) ? 2 * D : D)                                          \
            + (size_t)((jt_) * 64 + r) * TD + lc * 8;                            \
        cp16(sb + 36864u + (uint32_t)(buf_) * (uint32_t)KVBUF                    \
             + (uint32_t)(comp * 9216 + r * APITCH + lc * 16), src);             \
    }                                                                            \
    asm volatile("cp.async.commit_group;" ::: "memory");                         \
} while (0)

    const int ktiles = 2 * qt + 2;
    KV_ISSUE(0, 0);                    // group 0: Q + KV tile 0
    if (ktiles > 1) KV_ISSUE(1, 1);    // group 1: KV tile 1

    // fragment address offsets (pitch 144)
    const uint32_t aoff = (uint32_t)((lane & 15) * APITCH + (lane >> 4) * 16);
    const uint32_t boff = (uint32_t)(((lane & 7) + ((lane >> 4) << 3)) * APITCH +
                                     ((lane >> 3) & 1) * 16);
    const uint32_t voff = (uint32_t)(((lane & 7) + (((lane >> 3) & 1) << 3)) * APITCH +
                                     (lane >> 4) * 16);
    const uint32_t qh_base = sb + (uint32_t)(wid * 16 * APITCH) + aoff;
    const uint32_t ql_base = qh_base + 18432;

    float o[8][4];
#pragma unroll
    for (int nj = 0; nj < 8; ++nj)
#pragma unroll
        for (int c = 0; c < 4; ++c) o[nj][c] = 0.0f;
    float m0 = -1e30f, m1 = -1e30f, l0 = 0.0f, l1 = 0.0f;

    for (int jt = 0; jt < ktiles; ++jt) {
        if (jt + 1 < ktiles)
            asm volatile("cp.async.wait_group 1;" ::: "memory");
        else
            asm volatile("cp.async.wait_group 0;" ::: "memory");
        __syncthreads();

        const uint32_t kvb = sb + 36864u + (uint32_t)(jt & 1) * (uint32_t)KVBUF;

        // ---- S = Q @ K^T (bf16x3; Q pre-scaled by 0.125) ----
        float s[8][4];
#pragma unroll
        for (int nj = 0; nj < 8; ++nj)
#pragma unroll
            for (int c = 0; c < 4; ++c) s[nj][c] = 0.0f;

#pragma unroll
        for (int kc = 0; kc < 4; ++kc) {
            uint32_t ah[4], al[4];
            ldm4(ah, qh_base + kc * 32);
            ldm4(al, ql_base + kc * 32);
#pragma unroll
            for (int kg = 0; kg < 4; ++kg) {
                uint32_t bh[4], bl[4];
                ldm4(bh, kvb + (uint32_t)(kg * 16 * APITCH) + boff + kc * 32);
                ldm4(bl, kvb + 9216u + (uint32_t)(kg * 16 * APITCH) + boff + kc * 32);
                mma16816(s[2 * kg],     ah, &bh[0]);
                mma16816(s[2 * kg],     ah, &bl[0]);
                mma16816(s[2 * kg],     al, &bh[0]);
                mma16816(s[2 * kg + 1], ah, &bh[2]);
                mma16816(s[2 * kg + 1], ah, &bl[2]);
                mma16816(s[2 * kg + 1], al, &bh[2]);
            }
        }

        // ---- causal mask (only the last two diagonal tiles need it) ----
        const int gr0 = q0 + wid * 16 + (lane >> 2);
        const int gr1 = gr0 + 8;
        if (jt >= 2 * qt) {
            const int k0 = jt * 64;
#pragma unroll
            for (int nj = 0; nj < 8; ++nj) {
                const int gc = k0 + nj * 8 + (lane & 3) * 2;
                if (gc     > gr0) s[nj][0] = -10000.0f;
                if (gc + 1 > gr0) s[nj][1] = -10000.0f;
                if (gc     > gr1) s[nj][2] = -10000.0f;
                if (gc + 1 > gr1) s[nj][3] = -10000.0f;
            }
        }

        // ---- streaming softmax ----
        float mx0 = -1e30f, mx1 = -1e30f;
#pragma unroll
        for (int nj = 0; nj < 8; ++nj) {
            mx0 = fmaxf(mx0, fmaxf(s[nj][0], s[nj][1]));
            mx1 = fmaxf(mx1, fmaxf(s[nj][2], s[nj][3]));
        }
        mx0 = fmaxf(mx0, __shfl_xor_sync(0xffffffffu, mx0, 1));
        mx0 = fmaxf(mx0, __shfl_xor_sync(0xffffffffu, mx0, 2));
        mx1 = fmaxf(mx1, __shfl_xor_sync(0xffffffffu, mx1, 1));
        mx1 = fmaxf(mx1, __shfl_xor_sync(0xffffffffu, mx1, 2));

        const float mn0 = fmaxf(m0, mx0), mn1 = fmaxf(m1, mx1);
        const float f0 = __expf(m0 - mn0), f1 = __expf(m1 - mn1);

        float rs0 = 0.0f, rs1 = 0.0f;
#pragma unroll
        for (int nj = 0; nj < 8; ++nj) {
            s[nj][0] = __expf(s[nj][0] - mn0);
            s[nj][1] = __expf(s[nj][1] - mn0);
            s[nj][2] = __expf(s[nj][2] - mn1);
            s[nj][3] = __expf(s[nj][3] - mn1);
            rs0 += s[nj][0] + s[nj][1];
            rs1 += s[nj][2] + s[nj][3];
        }
        rs0 += __shfl_xor_sync(0xffffffffu, rs0, 1);
        rs0 += __shfl_xor_sync(0xffffffffu, rs0, 2);
        rs1 += __shfl_xor_sync(0xffffffffu, rs1, 1);
        rs1 += __shfl_xor_sync(0xffffffffu, rs1, 2);

        l0 = l0 * f0 + rs0;  m0 = mn0;
        l1 = l1 * f1 + rs1;  m1 = mn1;
#pragma unroll
        for (int nj = 0; nj < 8; ++nj) {
            o[nj][0] *= f0; o[nj][1] *= f0;
            o[nj][2] *= f1; o[nj][3] *= f1;
        }

        // ---- O += P @ V (P packed in-register, bf16x3) ----
#pragma unroll
        for (int kc2 = 0; kc2 < 4; ++kc2) {
            uint32_t ph[4], pl[4];
            ph[0] = pack_bf(s[2 * kc2][0],     s[2 * kc2][1]);
            ph[1] = pack_bf(s[2 * kc2][2],     s[2 * kc2][3]);
            ph[2] = pack_bf(s[2 * kc2 + 1][0], s[2 * kc2 + 1][1]);
            ph[3] = pack_bf(s[2 * kc2 + 1][2], s[2 * kc2 + 1][3]);
            pl[0] = pack_lo(ph[0], s[2 * kc2][0],     s[2 * kc2][1]);
            pl[1] = pack_lo(ph[1], s[2 * kc2][2],     s[2 * kc2][3]);
            pl[2] = pack_lo(ph[2], s[2 * kc2 + 1][0], s[2 * kc2 + 1][1]);
            pl[3] = pack_lo(ph[3], s[2 * kc2 + 1][2], s[2 * kc2 + 1][3]);
#pragma unroll
            for (int vg = 0; vg < 4; ++vg) {
                uint32_t vh[4], vl[4];
                ldm4t(vh, kvb + 18432u + (uint32_t)(kc2 * 16 * APITCH) + voff + vg * 32);
                ldm4t(vl, kvb + 27648u + (uint32_t)(kc2 * 16 * APITCH) + voff + vg * 32);
                mma16816(o[2 * vg],     ph, &vh[0]);
                mma16816(o[2 * vg],     ph, &vl[0]);
                mma16816(o[2 * vg],     pl, &vh[0]);
                mma16816(o[2 * vg + 1], ph, &vh[2]);
                mma16816(o[2 * vg + 1], ph, &vl[2]);
                mma16816(o[2 * vg + 1], pl, &vh[2]);
            }
        }

        __syncthreads();   // readers done before reissuing into this buffer
        if (jt + 2 < ktiles) KV_ISSUE(jt + 2, (jt & 1));
    }
#undef KV_ISSUE

    // ---- epilogue: normalize, split bf16 hi/lo, merged-head layout ----
    const float i0 = 1.0f / l0, i1 = 1.0f / l1;
    const int r0 = q0 + wid * 16 + (lane >> 2);
    const size_t g0 = ((size_t)b * S + r0) * D + h * HD;
    const size_t g1 = g0 + (size_t)8 * D;
#pragma unroll
    for (int nj = 0; nj < 8; ++nj) {
        const int col = nj * 8 + (lane & 3) * 2;
        const float v0 = o[nj][0] * i0, v1 = o[nj][1] * i0;
        const float v2 = o[nj][2] * i1, v3 = o[nj][3] * i1;
        const uint32_t h01 = pack_bf(v0, v1), h23 = pack_bf(v2, v3);
        *(uint32_t*)&Ahd[g0 + col] = h01;
        *(uint32_t*)&Ahd[g1 + col] = h23;
        *(uint32_t*)&Ald[g0 + col] = pack_lo(h01, v0, v1);
        *(uint32_t*)&Ald[g1 + col] = pack_lo(h23, v2, v3);
    }
}

// =====================================================================
// launch
// =====================================================================
extern "C" void kernel_launch(void* const* d_in, const int* in_sizes, int n_in,
                              void* d_out, int out_size)
{
    const float* hs     = (const float*)d_in[0];
    const float* w_attn = (const float*)d_in[1];
    const float* b_attn = (const float*)d_in[2];
    const float* w_proj = (const float*)d_in[3];
    const float* b_proj = (const float*)d_in[4];
    float* out = (float*)d_out;

    __nv_bfloat16 *qkvh, *qkvl, *Ah, *Al, *Bh, *Bl;
    cudaGetSymbolAddress((void**)&qkvh, g_qkvh);
    cudaGetSymbolAddress((void**)&qkvl, g_qkvl);
    cudaGetSymbolAddress((void**)&Ah, g_Ah);
    cudaGetSymbolAddress((void**)&Al, g_Al);
    cudaGetSymbolAddress((void**)&Bh, g_Bh);
    cudaGetSymbolAddress((void**)&Bl, g_Bl);

    cudaFuncSetAttribute(gemm_bf16x3_kernel,
                         cudaFuncAttributeMaxDynamicSharedMemorySize, GEMM_SMEM);
    cudaFuncSetAttribute(attn_mma_kernel,
                         cudaFuncAttributeMaxDynamicSharedMemorySize, ATTN2_SMEM);

    // --- stage 1: QKV projection -> bf16 hi/lo split, Q pre-scaled by 0.125 ---
    split_bf16_kernel<<<(M * D / 4 + 255) / 256, 256>>>(hs, Ah, Al, M * D / 4);
    transpose_split_kernel<<<dim3(TD / 32, D / 32), dim3(32, 8)>>>(w_attn, Bh, Bl, D, TD);
    dim3 g1(TD / 128, M / 128);        // (24, 64)
    gemm_bf16x3_kernel<<<g1, 128, GEMM_SMEM>>>(Ah, Al, Bh, Bl, b_attn,
                                               nullptr, qkvh, qkvl, TD, D, D);

    // --- stage 2: causal flash attention (cp.async double-buffered, coalesced) ---
    dim3 g2(S / 128, H, Bsz);          // (16, 16, 4)
    attn_mma_kernel<<<g2, 256, ATTN2_SMEM>>>(qkvh, qkvl, Ah, Al);

    // --- stage 3: output projection -> fp32 out ---
    transpose_split_kernel<<<dim3(D / 32, D / 32), dim3(32, 8)>>>(w_proj, Bh, Bl, D, D);
    dim3 g3(D / 128, M / 128);         // (8, 64)
    gemm_bf16x3_kernel<<<g3, 128, GEMM_SMEM>>>(Ah, Al, Bh, Bl, b_proj,
                                               out, nullptr, nullptr, D, D, 0);
}